// round 10
// baseline (speedup 1.0000x reference)
#include <cuda_runtime.h>
#include <cuda_bf16.h>
#include <math.h>
#include <stdint.h>

// Problem constants
#define CC   1024
#define SS   16
#define DD   512
#define RR_T (CC*SS)        // 16384 rows

// GEMM tiling: block 128(M) x 128(N), K-chunk 64 bf16, 256 threads (8 warps)
#define MT 128
#define NTB 128
#define KC 64
#define NCHUNK (DD/KC)      // 8
#define NBLK (CC/NTB)       // 8

// Dynamic smem: 2 stages x (A 16K + B 16K) + epilogue invnm
#define STG      32768
#define OFF_B    16384
#define OFF_INM  65536      // 128 floats
#define DSMEM    66048

// Device scratch (no cudaMalloc allowed)
__device__ __align__(1024) __nv_bfloat16 g_xhi[RR_T*DD];   // 16.8 MB
__device__ __align__(1024) __nv_bfloat16 g_mhi[CC*DD];     // 1 MB
__device__ __align__(128) float g_nx[RR_T];
__device__ __align__(128) float g_invnx[RR_T];
__device__ __align__(128) float g_nm[CC];
__device__ __align__(128) float g_invnm[CC];
__device__ __align__(128) float g_dotm[RR_T];              // exact fp32 diag dot
__device__ __align__(128) float g_psum[RR_T];              // atomic per-row exp-sums

// ---------------------------------------------------------------------------
__device__ __forceinline__ uint32_t smem_u32(const void* p) {
    uint32_t a;
    asm("{ .reg .u64 t; cvta.to.shared.u64 t, %1; cvt.u32.u64 %0, t; }"
        : "=r"(a) : "l"(p));
    return a;
}
#define SWZ(o) ((o) ^ (((o) >> 3) & 0x70))

__device__ __forceinline__ void cpa16(uint32_t dst, const void* src) {
    asm volatile("cp.async.cg.shared.global [%0], [%1], 16;"
                 :: "r"(dst), "l"(src) : "memory");
}
__device__ __forceinline__ void ldsm_x4(uint32_t* r, uint32_t addr) {
    asm volatile("ldmatrix.sync.aligned.m8n8.x4.shared.b16 {%0,%1,%2,%3}, [%4];"
                 : "=r"(r[0]), "=r"(r[1]), "=r"(r[2]), "=r"(r[3]) : "r"(addr));
}
__device__ __forceinline__ void ldsm_x4t(uint32_t* r, uint32_t addr) {
    asm volatile("ldmatrix.sync.aligned.m8n8.x4.trans.shared.b16 {%0,%1,%2,%3}, [%4];"
                 : "=r"(r[0]), "=r"(r[1]), "=r"(r[2]), "=r"(r[3]) : "r"(addr));
}
__device__ __forceinline__ void mma16816(float* d, const uint32_t* a, const uint32_t* b) {
    asm volatile(
        "mma.sync.aligned.m16n8k16.row.col.f32.bf16.bf16.f32 "
        "{%0,%1,%2,%3}, {%4,%5,%6,%7}, {%8,%9}, {%0,%1,%2,%3};"
        : "+f"(d[0]), "+f"(d[1]), "+f"(d[2]), "+f"(d[3])
        : "r"(a[0]), "r"(a[1]), "r"(a[2]), "r"(a[3]), "r"(b[0]), "r"(b[1]));
}

// FMA-pipe exp for args in [-2wp, 0]
__device__ __forceinline__ float fexp(float u) {
    float t = u * 1.4426950408889634f;
    int   ki = __float2int_rn(t);
    float f = t - (float)ki;
    float p = 1.3333558e-3f;
    p = fmaf(p, f, 9.6181291e-3f);
    p = fmaf(p, f, 5.5504109e-2f);
    p = fmaf(p, f, 2.4022651e-1f);
    p = fmaf(p, f, 6.9314718e-1f);
    p = fmaf(p, f, 1.0f);
    return p * __int_as_float((ki + 127) << 23);
}

__device__ __forceinline__ float d4(float4 a, float4 b) {
    return fmaf(a.x, b.x, fmaf(a.y, b.y, fmaf(a.z, b.z, a.w * b.w)));
}

// ---------------------------------------------------------------------------
// Kernel A: bf16 casts, means, norms, exact fp32 diagonal dots, psum zeroing.
// 1024 blocks x 128 threads; thread t owns dims [4t, 4t+4) of class j.
// ---------------------------------------------------------------------------
__global__ __launch_bounds__(128)
void prep_kernel(const float* __restrict__ x) {
    __shared__ float sq[SS * 128];   // 8 KB: per-thread |x|^2 partials
    __shared__ float dm[SS * 128];   // 8 KB: per-thread x.mean partials
    __shared__ float red[4];
    const int j = blockIdx.x;
    const int t = threadIdx.x;
    const float4* x4 = (const float4*)(x + (size_t)j * SS * DD);

    if (t < SS) g_psum[j * SS + t] = 0.f;

    float4 xv[SS];
    float4 msum = make_float4(0.f, 0.f, 0.f, 0.f);
    #pragma unroll
    for (int i = 0; i < SS; i++) {
        xv[i] = x4[i * 128 + t];
        msum.x += xv[i].x; msum.y += xv[i].y;
        msum.z += xv[i].z; msum.w += xv[i].w;
    }
    const float4 mean = make_float4(msum.x * (1.f/16.f), msum.y * (1.f/16.f),
                                    msum.z * (1.f/16.f), msum.w * (1.f/16.f));

    // store bf16 mean (4 values -> uint2)
    {
        __nv_bfloat162 lo = __float22bfloat162_rn(make_float2(mean.x, mean.y));
        __nv_bfloat162 hi = __float22bfloat162_rn(make_float2(mean.z, mean.w));
        *(__nv_bfloat162*)&g_mhi[(size_t)j * DD + 4 * t]     = lo;
        *(__nv_bfloat162*)&g_mhi[(size_t)j * DD + 4 * t + 2] = hi;
    }
    #pragma unroll
    for (int i = 0; i < SS; i++) {
        __nv_bfloat162 lo = __float22bfloat162_rn(make_float2(xv[i].x, xv[i].y));
        __nv_bfloat162 hi = __float22bfloat162_rn(make_float2(xv[i].z, xv[i].w));
        size_t base = (size_t)(j * SS + i) * DD + 4 * t;
        *(__nv_bfloat162*)&g_xhi[base]     = lo;
        *(__nv_bfloat162*)&g_xhi[base + 2] = hi;
        sq[i * 128 + t] = d4(xv[i], xv[i]);
        dm[i * 128 + t] = d4(xv[i], mean);
    }

    // block-reduce |mean|^2 over 128 threads
    float pm = d4(mean, mean);
    #pragma unroll
    for (int o = 16; o; o >>= 1) pm += __shfl_xor_sync(0xffffffffu, pm, o);
    if ((t & 31) == 0) red[t >> 5] = pm;
    __syncthreads();
    if (t == 0) {
        float nm2 = red[0] + red[1] + red[2] + red[3];
        float nm = sqrtf(nm2);
        g_nm[j] = nm;
        g_invnm[j] = 1.f / nm;
    }

    // per-row reductions: row = t>>3, 8 lanes per row, 16 partials each
    const int row = t >> 3, s = t & 7;
    float a = 0.f, b = 0.f;
    #pragma unroll
    for (int k = 0; k < 16; k++) {
        a += sq[row * 128 + s + 8 * k];
        b += dm[row * 128 + s + 8 * k];
    }
    #pragma unroll
    for (int o = 4; o; o >>= 1) {
        a += __shfl_xor_sync(0xffffffffu, a, o);
        b += __shfl_xor_sync(0xffffffffu, b, o);
    }
    if (s == 0) {
        float nx = sqrtf(a);
        g_nx[j * SS + row] = nx;
        g_invnx[j * SS + row] = 1.f / nx;
        g_dotm[j * SS + row] = b;
    }
}

// ---------------------------------------------------------------------------
// Kernel B: bf16 HMMA GEMM (mma.sync) + fused off-diagonal exp-sum epilogue
// ---------------------------------------------------------------------------
__device__ __forceinline__ void stage_load(uint32_t base, int c, int r0, int n0, int tid) {
    const int koff = c * KC;
    #pragma unroll
    for (int q = 0; q < 4; q++) {
        int qa = tid + 256 * q;
        int row = qa >> 3, qq = qa & 7;
        uint32_t sw = SWZ(row * 128 + qq * 16);
        cpa16(base + sw,           g_xhi + (size_t)(r0 + row) * DD + koff + qq * 8);
        cpa16(base + OFF_B + sw,   g_mhi + (size_t)(n0 + row) * DD + koff + qq * 8);
    }
}

__global__ __launch_bounds__(256, 2)
void gemm_lse_kernel(const float* __restrict__ wptr) {
    extern __shared__ __align__(1024) char sm[];
    const uint32_t sb = smem_u32(sm);
    const int tid  = threadIdx.x;
    const int lane = tid & 31;
    const int wid  = tid >> 5;
    const int warpM = wid & 3;         // 0..3  (32-row tiles)
    const int warpN = wid >> 2;        // 0..1  (64-col tiles)
    const int r0 = blockIdx.x * MT;
    const int n0 = blockIdx.y * NTB;

    float* s_invnm = (float*)(sm + OFF_INM);
    if (tid < NTB) s_invnm[tid] = g_invnm[n0 + tid];

    float acc[2][8][4];
    #pragma unroll
    for (int mf = 0; mf < 2; mf++)
        #pragma unroll
        for (int nf = 0; nf < 8; nf++)
            #pragma unroll
            for (int q = 0; q < 4; q++) acc[mf][nf][q] = 0.f;

    const int g  = lane >> 3;          // ldmatrix address group
    const int ri = lane & 7;
    const int mrow = warpM * 32;
    const int arow0 = mrow + (g & 1) * 8 + ri;           // + mf*16
    const int acol0 = (g >> 1) * 16;                     // + kk*32
    const int brow0 = warpN * 64 + (g >> 1) * 8 + ri;    // + nf2*16
    const int bcol0 = (g & 1) * 16;                      // + kk*32

    stage_load(sb, 0, r0, n0, tid);
    asm volatile("cp.async.commit_group;" ::: "memory");

    for (int c = 0; c < NCHUNK; ++c) {
        if (c + 1 < NCHUNK) {
            stage_load(sb + ((c + 1) & 1) * STG, c + 1, r0, n0, tid);
            asm volatile("cp.async.commit_group;" ::: "memory");
            asm volatile("cp.async.wait_group 1;" ::: "memory");
        } else {
            asm volatile("cp.async.wait_group 0;" ::: "memory");
        }
        __syncthreads();

        const uint32_t aB = sb + (c & 1) * STG;
        const uint32_t bB = aB + OFF_B;
        #pragma unroll
        for (int kk = 0; kk < 4; kk++) {
            uint32_t a[2][4], b[8][2];
            #pragma unroll
            for (int mf = 0; mf < 2; mf++)
                ldsm_x4(a[mf], aB + SWZ((arow0 + mf * 16) * 128 + kk * 32 + acol0));
            #pragma unroll
            for (int nf2 = 0; nf2 < 4; nf2++) {
                uint32_t t[4];
                ldsm_x4t(t, bB + SWZ((brow0 + nf2 * 16) * 128 + kk * 32 + bcol0));
                b[nf2 * 2][0]     = t[0]; b[nf2 * 2][1]     = t[1];
                b[nf2 * 2 + 1][0] = t[2]; b[nf2 * 2 + 1][1] = t[3];
            }
            #pragma unroll
            for (int mf = 0; mf < 2; mf++)
                #pragma unroll
                for (int nf = 0; nf < 8; nf++)
                    mma16816(acc[mf][nf], a[mf], b[nf]);
        }
        __syncthreads();
    }

    // -------- epilogue: off-diagonal exp-sum per row (atomic into g_psum) ----
    const float wv = wptr[0];
    const float wp = fmaxf(wv, 0.f) + log1pf(expf(-fabsf(wv)));

    float invr[2][2];
    int jcl[2][2];
    #pragma unroll
    for (int mf = 0; mf < 2; mf++)
        #pragma unroll
        for (int fr = 0; fr < 2; fr++) {
            int r = r0 + mrow + mf * 16 + fr * 8 + (lane >> 2);
            invr[mf][fr] = g_invnx[r];
            jcl[mf][fr]  = r >> 4;
        }

    float rsum[2][2] = {{0.f, 0.f}, {0.f, 0.f}};
    #pragma unroll
    for (int mf = 0; mf < 2; mf++)
        #pragma unroll
        for (int nf = 0; nf < 8; nf++) {
            const int nl0 = warpN * 64 + nf * 8 + (lane & 3) * 2;
            const float im0 = s_invnm[nl0], im1 = s_invnm[nl0 + 1];
            #pragma unroll
            for (int fr = 0; fr < 2; fr++) {
                const float a0 = acc[mf][nf][fr * 2 + 0];
                const float a1 = acc[mf][nf][fr * 2 + 1];
                const float iv = invr[mf][fr];
                const int jc = jcl[mf][fr];
                if (n0 + nl0 != jc)
                    rsum[mf][fr] += fexp(fmaf(wp, a0 * iv * im0, -wp));
                if (n0 + nl0 + 1 != jc)
                    rsum[mf][fr] += fexp(fmaf(wp, a1 * iv * im1, -wp));
            }
        }

    // reduce over the 4 lanes of each quad (same row, different cols), then REDG
    #pragma unroll
    for (int mf = 0; mf < 2; mf++)
        #pragma unroll
        for (int fr = 0; fr < 2; fr++) {
            float v = rsum[mf][fr];
            v += __shfl_xor_sync(0xffffffffu, v, 1);
            v += __shfl_xor_sync(0xffffffffu, v, 2);
            if ((lane & 3) == 0)
                atomicAdd(&g_psum[r0 + mrow + mf * 16 + fr * 8 + (lane >> 2)], v);
        }
}

// ---------------------------------------------------------------------------
// Kernel C: single block — diagonal term, per-row loss, full reduce, write out
// ---------------------------------------------------------------------------
__global__ __launch_bounds__(1024)
void combine_kernel(const float* __restrict__ wptr, float* __restrict__ out) {
    __shared__ float red[32];
    const int t = threadIdx.x;
    const float wv = wptr[0];
    const float wp = fmaxf(wv, 0.f) + log1pf(expf(-fabsf(wv)));

    float acc = 0.f;
    #pragma unroll
    for (int k = 0; k < RR_T / 1024; k++) {
        const int r = t + 1024 * k;
        float tot = g_psum[r];
        const float nx = g_nx[r];
        const float nx2 = nx * nx;
        const float nm = g_nm[r >> 4];
        const float dmv = g_dotm[r];
        float dotpos = fmaf(16.f, dmv, -nx2) * (1.f / 15.f);
        float t2 = fmaxf(fmaf(256.f, nm * nm, fmaf(-32.f, dmv, nx2)), 0.f);
        float nloo = sqrtf(t2) * (1.f / 15.f);
        float simp = dotpos / fmaxf(nx * nloo, 1e-8f);
        tot += fexp(fmaf(wp, simp, -wp));
        acc += fmaf(-wp, simp, wp) + logf(tot);
    }
    #pragma unroll
    for (int o = 16; o; o >>= 1) acc += __shfl_xor_sync(0xffffffffu, acc, o);
    if ((t & 31) == 0) red[t >> 5] = acc;
    __syncthreads();
    if (t < 32) {
        float s = red[t];
        #pragma unroll
        for (int o = 16; o; o >>= 1) s += __shfl_xor_sync(0xffffffffu, s, o);
        if (t == 0) out[0] = s * (1.f / (float)RR_T);
    }
}

// ---------------------------------------------------------------------------
extern "C" void kernel_launch(void* const* d_in, const int* in_sizes, int n_in,
                              void* d_out, int out_size) {
    (void)in_sizes; (void)n_in; (void)out_size;
    const float* x = (const float*)d_in[0];
    const float* w = (const float*)d_in[1];
    float* out = (float*)d_out;

    cudaFuncSetAttribute(gemm_lse_kernel,
                         cudaFuncAttributeMaxDynamicSharedMemorySize, DSMEM);

    prep_kernel<<<CC, 128>>>(x);
    dim3 grid(RR_T / MT, CC / NTB);   // 128 x 8
    gemm_lse_kernel<<<grid, 256, DSMEM>>>(w);
    combine_kernel<<<1, 1024>>>(w, out);
}

// round 14
// speedup vs baseline: 1.7244x; 1.7244x over previous
#include <cuda_runtime.h>
#include <cuda_bf16.h>
#include <math.h>
#include <stdint.h>

// Problem constants
#define CC   1024
#define SS   16
#define DD   512
#define RR_T (CC*SS)        // 16384 rows

// GEMM tiling: block 128(M) x 128(N), K-chunk 64 bf16, 256 threads (8 warps)
#define MT 128
#define NTB 128
#define KC 64
#define NCHUNK (DD/KC)      // 8
#define NBLK (CC/NTB)       // 8

// Dynamic smem: 2 stages x (A 16K + B 16K) + epilogue
#define STG      32768
#define OFF_B    16384
#define OFF_INM  65536      // 128 floats
#define OFF_PS   66048      // 128*2 floats
#define DSMEM    67072

// Device scratch (no cudaMalloc allowed)
__device__ __align__(1024) __nv_bfloat16 g_xhi[RR_T*DD];   // 16.8 MB
__device__ __align__(1024) __nv_bfloat16 g_mhi[CC*DD];     // 1 MB
__device__ __align__(128) float g_nx[RR_T];
__device__ __align__(128) float g_invnx[RR_T];
__device__ __align__(128) float g_nm[CC];
__device__ __align__(128) float g_invnm[CC];
__device__ __align__(128) float g_dotm[RR_T];              // exact fp32 diag dot
__device__ __align__(128) float g_psum[RR_T*NBLK];         // 512 KB, written once each
__device__ __align__(128) float g_part[32];                // combine block partials
__device__ unsigned int g_done;                            // self-resetting counter

// ---------------------------------------------------------------------------
__device__ __forceinline__ uint32_t smem_u32(const void* p) {
    uint32_t a;
    asm("{ .reg .u64 t; cvta.to.shared.u64 t, %1; cvt.u32.u64 %0, t; }"
        : "=r"(a) : "l"(p));
    return a;
}
#define SWZ(o) ((o) ^ (((o) >> 3) & 0x70))

__device__ __forceinline__ void cpa16(uint32_t dst, const void* src) {
    asm volatile("cp.async.cg.shared.global [%0], [%1], 16;"
                 :: "r"(dst), "l"(src) : "memory");
}
__device__ __forceinline__ void ldsm_x4(uint32_t* r, uint32_t addr) {
    asm volatile("ldmatrix.sync.aligned.m8n8.x4.shared.b16 {%0,%1,%2,%3}, [%4];"
                 : "=r"(r[0]), "=r"(r[1]), "=r"(r[2]), "=r"(r[3]) : "r"(addr));
}
__device__ __forceinline__ void ldsm_x4t(uint32_t* r, uint32_t addr) {
    asm volatile("ldmatrix.sync.aligned.m8n8.x4.trans.shared.b16 {%0,%1,%2,%3}, [%4];"
                 : "=r"(r[0]), "=r"(r[1]), "=r"(r[2]), "=r"(r[3]) : "r"(addr));
}
__device__ __forceinline__ void mma16816(float* d, const uint32_t* a, const uint32_t* b) {
    asm volatile(
        "mma.sync.aligned.m16n8k16.row.col.f32.bf16.bf16.f32 "
        "{%0,%1,%2,%3}, {%4,%5,%6,%7}, {%8,%9}, {%0,%1,%2,%3};"
        : "+f"(d[0]), "+f"(d[1]), "+f"(d[2]), "+f"(d[3])
        : "r"(a[0]), "r"(a[1]), "r"(a[2]), "r"(a[3]), "r"(b[0]), "r"(b[1]));
}

// FMA-pipe exp for args in [-2wp, 0]
__device__ __forceinline__ float fexp(float u) {
    float t = u * 1.4426950408889634f;
    int   ki = __float2int_rn(t);
    float f = t - (float)ki;
    float p = 1.3333558e-3f;
    p = fmaf(p, f, 9.6181291e-3f);
    p = fmaf(p, f, 5.5504109e-2f);
    p = fmaf(p, f, 2.4022651e-1f);
    p = fmaf(p, f, 6.9314718e-1f);
    p = fmaf(p, f, 1.0f);
    return p * __int_as_float((ki + 127) << 23);
}

__device__ __forceinline__ float d4(float4 a, float4 b) {
    return fmaf(a.x, b.x, fmaf(a.y, b.y, fmaf(a.z, b.z, a.w * b.w)));
}
__device__ __forceinline__ uint32_t bf2u(float a, float b) {
    __nv_bfloat162 v = __float22bfloat162_rn(make_float2(a, b));
    return *(uint32_t*)&v;
}

// ---------------------------------------------------------------------------
// Kernel A: bf16 casts, means, norms, exact fp32 diagonal dots.
// 1024 blocks x 128 threads; thread t owns dims [4t, 4t+4) of class j.
// ---------------------------------------------------------------------------
__global__ __launch_bounds__(128)
void prep_kernel(const float* __restrict__ x) {
    __shared__ float sq[SS * 128];   // 8 KB
    __shared__ float dm[SS * 128];   // 8 KB
    __shared__ float red[4];
    const int j = blockIdx.x;
    const int t = threadIdx.x;
    const float4* x4 = (const float4*)(x + (size_t)j * SS * DD);

    float4 xv[SS];
    float4 msum = make_float4(0.f, 0.f, 0.f, 0.f);
    #pragma unroll
    for (int i = 0; i < SS; i++) {
        xv[i] = x4[i * 128 + t];
        msum.x += xv[i].x; msum.y += xv[i].y;
        msum.z += xv[i].z; msum.w += xv[i].w;
    }
    const float4 mean = make_float4(msum.x * (1.f/16.f), msum.y * (1.f/16.f),
                                    msum.z * (1.f/16.f), msum.w * (1.f/16.f));

    *(uint2*)&g_mhi[(size_t)j * DD + 4 * t] =
        make_uint2(bf2u(mean.x, mean.y), bf2u(mean.z, mean.w));

    #pragma unroll
    for (int i = 0; i < SS; i++) {
        *(uint2*)&g_xhi[(size_t)(j * SS + i) * DD + 4 * t] =
            make_uint2(bf2u(xv[i].x, xv[i].y), bf2u(xv[i].z, xv[i].w));
        sq[i * 128 + t] = d4(xv[i], xv[i]);
        dm[i * 128 + t] = d4(xv[i], mean);
    }

    // block-reduce |mean|^2 over 128 threads
    float pm = d4(mean, mean);
    #pragma unroll
    for (int o = 16; o; o >>= 1) pm += __shfl_xor_sync(0xffffffffu, pm, o);
    if ((t & 31) == 0) red[t >> 5] = pm;
    __syncthreads();
    if (t == 0) {
        float nm2 = red[0] + red[1] + red[2] + red[3];
        float nm = sqrtf(nm2);
        g_nm[j] = nm;
        g_invnm[j] = 1.f / nm;
    }

    // per-row reductions: row = t>>3, 8 lanes per row, 16 partials each
    const int row = t >> 3, s = t & 7;
    float a = 0.f, b = 0.f;
    #pragma unroll
    for (int k = 0; k < 16; k++) {
        a += sq[row * 128 + s + 8 * k];
        b += dm[row * 128 + s + 8 * k];
    }
    #pragma unroll
    for (int o = 4; o; o >>= 1) {
        a += __shfl_xor_sync(0xffffffffu, a, o);
        b += __shfl_xor_sync(0xffffffffu, b, o);
    }
    if (s == 0) {
        float nx = sqrtf(a);
        g_nx[j * SS + row] = nx;
        g_invnx[j * SS + row] = 1.f / nx;
        g_dotm[j * SS + row] = b;
    }
}

// ---------------------------------------------------------------------------
// Kernel B: bf16 HMMA GEMM (mma.sync) + fused off-diagonal exp-sum epilogue
// ---------------------------------------------------------------------------
__device__ __forceinline__ void stage_load(uint32_t base, int c, int r0, int n0, int tid) {
    const int koff = c * KC;
    #pragma unroll
    for (int q = 0; q < 4; q++) {
        int qa = tid + 256 * q;
        int row = qa >> 3, qq = qa & 7;
        uint32_t sw = SWZ(row * 128 + qq * 16);
        cpa16(base + sw,           g_xhi + (size_t)(r0 + row) * DD + koff + qq * 8);
        cpa16(base + OFF_B + sw,   g_mhi + (size_t)(n0 + row) * DD + koff + qq * 8);
    }
}

__global__ __launch_bounds__(256, 2)
void gemm_lse_kernel(const float* __restrict__ wptr) {
    extern __shared__ __align__(1024) char sm[];
    const uint32_t sb = smem_u32(sm);
    const int tid  = threadIdx.x;
    const int lane = tid & 31;
    const int wid  = tid >> 5;
    const int warpM = wid & 3;         // 0..3  (32-row tiles)
    const int warpN = wid >> 2;        // 0..1  (64-col tiles)
    const int r0 = blockIdx.x * MT;
    const int n0 = blockIdx.y * NTB;

    float* s_invnm = (float*)(sm + OFF_INM);
    float* s_ps    = (float*)(sm + OFF_PS);
    if (tid < NTB) s_invnm[tid] = g_invnm[n0 + tid];

    float acc[2][8][4];
    #pragma unroll
    for (int mf = 0; mf < 2; mf++)
        #pragma unroll
        for (int nf = 0; nf < 8; nf++)
            #pragma unroll
            for (int q = 0; q < 4; q++) acc[mf][nf][q] = 0.f;

    const int g  = lane >> 3;          // ldmatrix address group
    const int ri = lane & 7;
    const int mrow = warpM * 32;
    const int arow0 = mrow + (g & 1) * 8 + ri;           // + mf*16
    const int acol0 = (g >> 1) * 16;                     // + kk*32
    const int brow0 = warpN * 64 + (g >> 1) * 8 + ri;    // + nf2*16
    const int bcol0 = (g & 1) * 16;                      // + kk*32

    stage_load(sb, 0, r0, n0, tid);
    asm volatile("cp.async.commit_group;" ::: "memory");

    for (int c = 0; c < NCHUNK; ++c) {
        if (c + 1 < NCHUNK) {
            stage_load(sb + ((c + 1) & 1) * STG, c + 1, r0, n0, tid);
            asm volatile("cp.async.commit_group;" ::: "memory");
            asm volatile("cp.async.wait_group 1;" ::: "memory");
        } else {
            asm volatile("cp.async.wait_group 0;" ::: "memory");
        }
        __syncthreads();

        const uint32_t aB = sb + (c & 1) * STG;
        const uint32_t bB = aB + OFF_B;
        #pragma unroll
        for (int kk = 0; kk < 4; kk++) {
            uint32_t a[2][4], b[8][2];
            #pragma unroll
            for (int mf = 0; mf < 2; mf++)
                ldsm_x4(a[mf], aB + SWZ((arow0 + mf * 16) * 128 + kk * 32 + acol0));
            #pragma unroll
            for (int nf2 = 0; nf2 < 4; nf2++) {
                uint32_t t[4];
                ldsm_x4t(t, bB + SWZ((brow0 + nf2 * 16) * 128 + kk * 32 + bcol0));
                b[nf2 * 2][0]     = t[0]; b[nf2 * 2][1]     = t[1];
                b[nf2 * 2 + 1][0] = t[2]; b[nf2 * 2 + 1][1] = t[3];
            }
            #pragma unroll
            for (int mf = 0; mf < 2; mf++)
                #pragma unroll
                for (int nf = 0; nf < 8; nf++)
                    mma16816(acc[mf][nf], a[mf], b[nf]);
        }
        __syncthreads();
    }

    // -------- epilogue: off-diagonal exp-sum per row (deterministic stores) --
    const float wv = wptr[0];
    const float wp = fmaxf(wv, 0.f) + log1pf(expf(-fabsf(wv)));

    float invr[2][2];
    int jcl[2][2];
    #pragma unroll
    for (int mf = 0; mf < 2; mf++)
        #pragma unroll
        for (int fr = 0; fr < 2; fr++) {
            int r = r0 + mrow + mf * 16 + fr * 8 + (lane >> 2);
            invr[mf][fr] = g_invnx[r];
            jcl[mf][fr]  = r >> 4;
        }

    float rsum[2][2] = {{0.f, 0.f}, {0.f, 0.f}};
    #pragma unroll
    for (int mf = 0; mf < 2; mf++)
        #pragma unroll
        for (int nf = 0; nf < 8; nf++) {
            const int nl0 = warpN * 64 + nf * 8 + (lane & 3) * 2;
            const float im0 = s_invnm[nl0], im1 = s_invnm[nl0 + 1];
            #pragma unroll
            for (int fr = 0; fr < 2; fr++) {
                const float a0 = acc[mf][nf][fr * 2 + 0];
                const float a1 = acc[mf][nf][fr * 2 + 1];
                const float iv = invr[mf][fr];
                const int jc = jcl[mf][fr];
                if (n0 + nl0 != jc)
                    rsum[mf][fr] += fexp(fmaf(wp, a0 * iv * im0, -wp));
                if (n0 + nl0 + 1 != jc)
                    rsum[mf][fr] += fexp(fmaf(wp, a1 * iv * im1, -wp));
            }
        }

    // reduce over the 4 lanes of each quad (same rows, different cols)
    #pragma unroll
    for (int mf = 0; mf < 2; mf++)
        #pragma unroll
        for (int fr = 0; fr < 2; fr++) {
            float v = rsum[mf][fr];
            v += __shfl_xor_sync(0xffffffffu, v, 1);
            v += __shfl_xor_sync(0xffffffffu, v, 2);
            if ((lane & 3) == 0)
                s_ps[(mrow + mf * 16 + fr * 8 + (lane >> 2)) * 2 + warpN] = v;
        }
    __syncthreads();

    if (tid < MT)
        g_psum[(size_t)(r0 + tid) * NBLK + blockIdx.y] =
            s_ps[tid * 2 + 0] + s_ps[tid * 2 + 1];
}

// ---------------------------------------------------------------------------
// Kernel C: diagonal term + per-row loss + two-level reduce; last block writes
// out[0] (threadfence-reduction pattern; counter self-resets via wrap at 31).
// ---------------------------------------------------------------------------
__global__ __launch_bounds__(512)
void combine_kernel(const float* __restrict__ wptr, float* __restrict__ out) {
    __shared__ float red[16];
    const int r = blockIdx.x * 512 + threadIdx.x;
    const float wv = wptr[0];
    const float wp = fmaxf(wv, 0.f) + log1pf(expf(-fabsf(wv)));

    float tot = 0.f;
    #pragma unroll
    for (int t = 0; t < NBLK; t++) tot += g_psum[(size_t)r * NBLK + t];

    const float nx = g_nx[r];
    const float nx2 = nx * nx;
    const float nm = g_nm[r >> 4];
    const float dmv = g_dotm[r];
    float dotpos = fmaf(16.f, dmv, -nx2) * (1.f / 15.f);
    float t2 = fmaxf(fmaf(256.f, nm * nm, fmaf(-32.f, dmv, nx2)), 0.f);
    float nloo = sqrtf(t2) * (1.f / 15.f);
    float simp = dotpos / fmaxf(nx * nloo, 1e-8f);
    tot += fexp(fmaf(wp, simp, -wp));
    float loss = fmaf(-wp, simp, wp) + logf(tot);

    // block reduce
    #pragma unroll
    for (int o = 16; o; o >>= 1) loss += __shfl_xor_sync(0xffffffffu, loss, o);
    const int wid = threadIdx.x >> 5, lane = threadIdx.x & 31;
    if (lane == 0) red[wid] = loss;
    __syncthreads();

    __shared__ bool amLast;
    if (threadIdx.x == 0) {
        float s = 0.f;
        #pragma unroll
        for (int k = 0; k < 16; k++) s += red[k];
        g_part[blockIdx.x] = s;
        __threadfence();
        unsigned int old = atomicInc(&g_done, 31u);  // wraps 31 -> 0: replay-safe
        amLast = (old == 31u);
    }
    __syncthreads();

    if (amLast && threadIdx.x < 32) {
        float v = g_part[threadIdx.x];
        #pragma unroll
        for (int o = 16; o; o >>= 1) v += __shfl_xor_sync(0xffffffffu, v, o);
        if (threadIdx.x == 0) out[0] = v * (1.f / (float)RR_T);
    }
}

// ---------------------------------------------------------------------------
extern "C" void kernel_launch(void* const* d_in, const int* in_sizes, int n_in,
                              void* d_out, int out_size) {
    (void)in_sizes; (void)n_in; (void)out_size;
    const float* x = (const float*)d_in[0];
    const float* w = (const float*)d_in[1];
    float* out = (float*)d_out;

    cudaFuncSetAttribute(gemm_lse_kernel,
                         cudaFuncAttributeMaxDynamicSharedMemorySize, DSMEM);

    prep_kernel<<<CC, 128>>>(x);
    dim3 grid(RR_T / MT, CC / NTB);   // 128 x 8
    gemm_lse_kernel<<<grid, 256, DSMEM>>>(w);
    combine_kernel<<<RR_T / 512, 512>>>(w, out);
}